// round 11
// baseline (speedup 1.0000x reference)
#include <cuda_runtime.h>
#include <cstdint>

#define BATCH 4
#define SEQ   1024
#define HNUM  16
#define HDIM  64
#define MTOT  4096
#define KDIM  1024

// Scratch (tf32-bit patterns stored as unsigned)
__device__ unsigned g_qt[MTOT*KDIM];
__device__ unsigned g_ct[MTOT*KDIM];
__device__ unsigned g_wqT[KDIM*KDIM];   // [n][k] K-major transposed weights
__device__ unsigned g_wkT[KDIM*KDIM];
__device__ unsigned g_wvT[KDIM*KDIM];
__device__ unsigned g_woT[KDIM*KDIM];
__device__ unsigned g_k[BATCH*HNUM*SEQ*HDIM];   // [B,H,Lkv,64] tf32 bits
__device__ unsigned g_v[BATCH*HNUM*SEQ*HDIM];
__device__ unsigned g_multi[MTOT*KDIM];         // concat head outputs, tf32 bits

__device__ __forceinline__ unsigned f2tf(float x){
    unsigned r; asm("cvt.rna.tf32.f32 %0, %1;" : "=r"(r) : "f"(x)); return r;
}
__device__ __forceinline__ float ex2(float x){
    float r; asm("ex2.approx.ftz.f32 %0, %1;" : "=f"(r) : "f"(x)); return r;
}
__device__ __forceinline__ void mma8(float* c, const unsigned* a, const unsigned* b){
    asm volatile("mma.sync.aligned.m16n8k8.row.col.f32.tf32.tf32.f32 "
        "{%0,%1,%2,%3}, {%4,%5,%6,%7}, {%8,%9}, {%0,%1,%2,%3};"
        : "+f"(c[0]),"+f"(c[1]),"+f"(c[2]),"+f"(c[3])
        : "r"(a[0]),"r"(a[1]),"r"(a[2]),"r"(a[3]),"r"(b[0]),"r"(b[1]));
}
__device__ __forceinline__ void cpa16(unsigned dst, const void* src){
    asm volatile("cp.async.cg.shared.global [%0], [%1], 16;" :: "r"(dst), "l"(src));
}
#define CP_COMMIT asm volatile("cp.async.commit_group;")
#define CP_WAIT1  asm volatile("cp.async.wait_group 1;")
#define CP_WAIT0  asm volatile("cp.async.wait_group 0;")

// ---------------------------------------------------------------------------
// Pre-pass 1: round inputs to tf32 bit patterns
// ---------------------------------------------------------------------------
__global__ __launch_bounds__(256) void cvt_in(const float* __restrict__ q,
                                              const float* __restrict__ c)
{
    int i = blockIdx.x * 256 + threadIdx.x;   // float4 index, 2M total
    const float* s; unsigned* d; int off;
    if (i < 1048576) { s = q; d = g_qt; off = i; }
    else             { s = c; d = g_ct; off = i - 1048576; }
    float4 v = ((const float4*)s)[off];
    ((uint4*)d)[off] = make_uint4(f2tf(v.x), f2tf(v.y), f2tf(v.z), f2tf(v.w));
}

// ---------------------------------------------------------------------------
// Pre-pass 2: transpose + round weights -> dense K-major [n][k]. (Proven.)
// ---------------------------------------------------------------------------
__global__ __launch_bounds__(256) void wt_pre(const float* __restrict__ wq,
    const float* __restrict__ wk, const float* __restrict__ wv,
    const float* __restrict__ wo)
{
    __shared__ float t[32][33];
    int id = blockIdx.x;
    int tx = threadIdx.x & 31, ty = threadIdx.x >> 5;
    int mi = id >> 10, tl = id & 1023;

    if (mi < 3) {
        const float* src = (mi==0 ? wq : mi==1 ? wk : wv);
        unsigned* dst = (mi==0 ? g_wqT : mi==1 ? g_wkT : g_wvT);
        int h = tl >> 6, tt = tl & 63;
        int tc = tt & 1, tr = tt >> 1;
        src += (size_t)h * 65536;       // [1024][64]
        dst += (size_t)h * 65536;       // [64][1024]
        #pragma unroll
        for (int j = 0; j < 4; j++)
            t[ty + j*8][tx] = src[(size_t)(tr*32 + ty + j*8)*64 + tc*32 + tx];
        __syncthreads();
        #pragma unroll
        for (int j = 0; j < 4; j++)
            dst[(size_t)(tc*32 + ty + j*8)*1024 + tr*32 + tx] = f2tf(t[tx][ty + j*8]);
    } else {
        int tc = tl & 31, tr = tl >> 5;
        #pragma unroll
        for (int j = 0; j < 4; j++)
            t[ty + j*8][tx] = wo[(size_t)(tr*32 + ty + j*8)*1024 + tc*32 + tx];
        __syncthreads();
        #pragma unroll
        for (int j = 0; j < 4; j++)
            g_woT[(size_t)(tc*32 + ty + j*8)*1024 + tr*32 + tx] = f2tf(t[tx][ty + j*8]);
    }
}

// ---------------------------------------------------------------------------
// Legacy-HMMA tf32 GEMM, CTA 128x128, 256 threads = 8 warps (4m x 2n) of
// R10's proven 32m x 64n warp tile. BK=32 double-buffered cp.async, occ 2
// (16 warps/SM). Halves L2 B-traffic vs the 64-row CTA (32 m-tiles not 64).
// PHASE 0: fused Q/K/V projections, grid.x=24 (sel = x>>3):
//          sel 0 -> fp32 Q to residual region; sel 1/2 -> tf32 K/V scratch.
// PHASE 1: out projection (A=g_multi, W=g_woT), fp32 + bo.
// ---------------------------------------------------------------------------
template<int PHASE>
__global__ __launch_bounds__(256,2) void gemmG(
    float* __restrict__ outbase,
    const float* __restrict__ bq, const float* __restrict__ bk,
    const float* __restrict__ bv, const float* __restrict__ bo)
{
    extern __shared__ unsigned sh[];        // A[2][128][36], B[2][128][36]
    unsigned* As = sh;                       // buffer stride 128*36
    unsigned* Bs = sh + 2*128*36;
    const unsigned sA = (unsigned)__cvta_generic_to_shared(As);
    const unsigned sB = (unsigned)__cvta_generic_to_shared(Bs);

    int sel, nb;
    const unsigned *Ap, *Wp;
    const float* bias;
    if (PHASE == 0) {
        sel = blockIdx.x >> 3; nb = blockIdx.x & 7;
        Ap = (sel == 0) ? g_qt : g_ct;
        Wp = (sel == 0) ? g_wqT : (sel == 1) ? g_wkT : g_wvT;
        bias = (sel == 0) ? bq : (sel == 1) ? bk : bv;
    } else {
        sel = 0; nb = blockIdx.x;
        Ap = g_multi; Wp = g_woT; bias = bo;
    }
    const int n0 = nb << 7;                  // 128-wide n tile
    const int m0 = blockIdx.y << 7;          // 128-wide m tile

    const int tid = threadIdx.x;
    const int lane = tid & 31, warp = tid >> 5;
    const int wm = warp & 3, wn = warp >> 2; // 4x2 warps of 32m x 64n
    const int lr = lane >> 2, lc = lane & 3;

    float acc[2][8][4] = {};

    // fill tasks: A 1024 chunks (4/thread), B 1024 chunks (4/thread); chunk=16B
    #define FILL(K0, BUFO)                                                    \
    {                                                                         \
        _Pragma("unroll")                                                     \
        for (int j = 0; j < 4; j++) {                                         \
            int c = tid + j*256, row = c >> 3, off = (c & 7) << 2;            \
            cpa16(sA + (unsigned)(((BUFO)*128*36 + row*36 + off)*4),          \
                  Ap + (size_t)(m0 + row)*KDIM + (K0) + off);                 \
            cpa16(sB + (unsigned)(((BUFO)*128*36 + row*36 + off)*4),          \
                  Wp + (size_t)(n0 + row)*KDIM + (K0) + off);                 \
        }                                                                     \
        CP_COMMIT;                                                            \
    }

    FILL(0, 0);

    for (int it = 0; it < 32; it++) {
        const int b = it & 1;
        __syncthreads();                       // other buffer consumed
        if (it < 31) {
            FILL((it+1) << 5, b ^ 1);
            CP_WAIT1;
        } else {
            CP_WAIT0;
        }
        __syncthreads();                       // tile it visible

        const unsigned* Ab = As + b*128*36;
        const unsigned* Bb = Bs + b*128*36;
        #pragma unroll
        for (int kk = 0; kk < 4; kk++) {
            const int cb = kk*8 + lc;
            unsigned a[2][4], bf[8][2];
            #pragma unroll
            for (int mi = 0; mi < 2; mi++) {
                int rb = (wm*32 + mi*16 + lr)*36 + cb;
                a[mi][0] = Ab[rb];       a[mi][1] = Ab[rb + 8*36];
                a[mi][2] = Ab[rb + 4];   a[mi][3] = Ab[rb + 8*36 + 4];
            }
            #pragma unroll
            for (int nf = 0; nf < 8; nf++) {
                int rb = (wn*64 + nf*8 + lr)*36 + cb;
                bf[nf][0] = Bb[rb];
                bf[nf][1] = Bb[rb + 4];
            }
            #pragma unroll
            for (int mi = 0; mi < 2; mi++)
                #pragma unroll
                for (int nf = 0; nf < 8; nf++)
                    mma8(acc[mi][nf], a[mi], bf[nf]);
        }
    }
    #undef FILL

    // epilogue
    #pragma unroll
    for (int mi = 0; mi < 2; mi++) {
        int r1 = m0 + wm*32 + mi*16 + lr;
        int r2 = r1 + 8;
        #pragma unroll
        for (int nf = 0; nf < 8; nf++) {
            int g = n0 + wn*64 + nf*8 + 2*lc;
            float b0 = bias[g], b1 = bias[g+1];
            float v00 = acc[mi][nf][0] + b0, v01 = acc[mi][nf][1] + b1;
            float v10 = acc[mi][nf][2] + b0, v11 = acc[mi][nf][3] + b1;
            if (PHASE == 1 || sel == 0) {
                float* dst = (PHASE == 1) ? outbase
                                          : outbase + (size_t)MTOT*KDIM;
                *(float2*)(dst + (size_t)r1*KDIM + g) = make_float2(v00, v01);
                *(float2*)(dst + (size_t)r2*KDIM + g) = make_float2(v10, v11);
            } else {
                unsigned* dst = (sel == 1) ? g_k : g_v;
                int h = g >> 6, wc = g & 63;
                *(uint2*)(dst + ((size_t)((r1 >> 10)*HNUM + h) << 16)
                              + (size_t)(r1 & 1023)*64 + wc) =
                    make_uint2(f2tf(v00), f2tf(v01));
                *(uint2*)(dst + ((size_t)((r2 >> 10)*HNUM + h) << 16)
                              + (size_t)(r2 & 1023)*64 + wc) =
                    make_uint2(f2tf(v10), f2tf(v11));
            }
        }
    }
}

// ---------------------------------------------------------------------------
// Per-warp flash attention (legacy tf32 mma) — unchanged from R4 (passing).
// ---------------------------------------------------------------------------
__global__ __launch_bounds__(256,2) void attn_tc(const float* __restrict__ Qres)
{
    extern __shared__ unsigned sh[];
    const unsigned sb = (unsigned)__cvta_generic_to_shared(sh);
    unsigned* Kb = sh;
    unsigned* Vb = sh + 2*64*68;
    const unsigned sbV = sb + 2*64*68*4;

    const int qb = blockIdx.x;
    const int bh = blockIdx.y;
    const int bb = bh >> 4, h = bh & 15;
    const int tid = threadIdx.x;
    const int lane = tid & 31, warp = tid >> 5;
    const int lr = lane >> 2, lc = lane & 3;

    const float SC = 0.125f * 1.44269504f;
    const float* qp = Qres + (size_t)(bb*SEQ + qb*128 + warp*16)*KDIM + (h<<6);
    unsigned Qa[8][4];
    #pragma unroll
    for (int kk = 0; kk < 8; kk++) {
        Qa[kk][0] = f2tf(SC * qp[(size_t)lr*KDIM     + kk*8 + lc]);
        Qa[kk][1] = f2tf(SC * qp[(size_t)(lr+8)*KDIM + kk*8 + lc]);
        Qa[kk][2] = f2tf(SC * qp[(size_t)lr*KDIM     + kk*8 + lc + 4]);
        Qa[kk][3] = f2tf(SC * qp[(size_t)(lr+8)*KDIM + kk*8 + lc + 4]);
    }

    const unsigned* kp = g_k + (size_t)bh*SEQ*HDIM;
    const unsigned* vp = g_v + (size_t)bh*SEQ*HDIM;
    const int krow = tid >> 4, kc4 = (tid & 15) << 2;

    {
        #pragma unroll
        for (int i = 0; i < 4; i++) {
            int r = krow + i*16;
            cpa16(sb  + (unsigned)((r*68 + kc4)*4), kp + r*64 + kc4);
            cpa16(sbV + (unsigned)((r*68 + kc4)*4), vp + r*64 + kc4);
        }
        CP_COMMIT;
    }

    float o[8][4] = {};
    float rm1 = -1e30f, rm2 = -1e30f, rl1 = 0.f, rl2 = 0.f;

    for (int kt = 0; kt < 16; kt++) {
        __syncthreads();
        if (kt < 15) {
            int buf = (kt+1) & 1;
            const unsigned* ks = kp + (size_t)(kt+1)*4096;
            const unsigned* vs = vp + (size_t)(kt+1)*4096;
            #pragma unroll
            for (int i = 0; i < 4; i++) {
                int r = krow + i*16;
                cpa16(sb  + (unsigned)(((buf*64 + r)*68 + kc4)*4), ks + r*64 + kc4);
                cpa16(sbV + (unsigned)(((buf*64 + r)*68 + kc4)*4), vs + r*64 + kc4);
            }
            CP_COMMIT;
            CP_WAIT1;
        } else {
            CP_WAIT0;
        }
        __syncthreads();

        const unsigned* K = Kb + (kt&1)*64*68;
        const unsigned* V = Vb + (kt&1)*64*68;

        float scf[8][4] = {};
        #pragma unroll
        for (int kk = 0; kk < 8; kk++) {
            #pragma unroll
            for (int nf = 0; nf < 8; nf++) {
                unsigned b[2];
                b[0] = K[(nf*8+lr)*68 + kk*8 + lc];
                b[1] = K[(nf*8+lr)*68 + kk*8 + lc + 4];
                mma8(scf[nf], Qa[kk], b);
            }
        }

        float m1 = -1e30f, m2 = -1e30f;
        #pragma unroll
        for (int nf = 0; nf < 8; nf++) {
            m1 = fmaxf(m1, fmaxf(scf[nf][0], scf[nf][1]));
            m2 = fmaxf(m2, fmaxf(scf[nf][2], scf[nf][3]));
        }
        m1 = fmaxf(m1, __shfl_xor_sync(0xffffffffu, m1, 1));
        m1 = fmaxf(m1, __shfl_xor_sync(0xffffffffu, m1, 2));
        m2 = fmaxf(m2, __shfl_xor_sync(0xffffffffu, m2, 1));
        m2 = fmaxf(m2, __shfl_xor_sync(0xffffffffu, m2, 2));
        float nm1 = fmaxf(rm1, m1), nm2 = fmaxf(rm2, m2);
        float cf1 = ex2(rm1 - nm1), cf2 = ex2(rm2 - nm2);
        rm1 = nm1; rm2 = nm2;

        float ls1 = 0.f, ls2 = 0.f;
        unsigned pa[8][4];
        #pragma unroll
        for (int nf = 0; nf < 8; nf++) {
            float p0 = ex2(scf[nf][0] - nm1); ls1 += p0;
            float p1 = ex2(scf[nf][1] - nm1); ls1 += p1;
            float p2 = ex2(scf[nf][2] - nm2); ls2 += p2;
            float p3 = ex2(scf[nf][3] - nm2); ls2 += p3;
            pa[nf][0] = f2tf(p0); pa[nf][1] = f2tf(p1);
            pa[nf][2] = f2tf(p2); pa[nf][3] = f2tf(p3);
        }
        ls1 += __shfl_xor_sync(0xffffffffu, ls1, 1);
        ls1 += __shfl_xor_sync(0xffffffffu, ls1, 2);
        ls2 += __shfl_xor_sync(0xffffffffu, ls2, 1);
        ls2 += __shfl_xor_sync(0xffffffffu, ls2, 2);
        rl1 = rl1*cf1 + ls1;
        rl2 = rl2*cf2 + ls2;

        #pragma unroll
        for (int nf = 0; nf < 8; nf++) {
            o[nf][0] *= cf1; o[nf][1] *= cf1;
            o[nf][2] *= cf2; o[nf][3] *= cf2;
        }

        #pragma unroll
        for (int kc = 0; kc < 8; kc++) {
            unsigned a[4] = { pa[kc][0], pa[kc][2], pa[kc][1], pa[kc][3] };
            #pragma unroll
            for (int nf = 0; nf < 8; nf++) {
                unsigned b[2];
                b[0] = V[(kc*8 + 2*lc    )*68 + nf*8 + lr];
                b[1] = V[(kc*8 + 2*lc + 1)*68 + nf*8 + lr];
                mma8(o[nf], a, b);
            }
        }
    }

    float inv1 = 1.f / rl1, inv2 = 1.f / rl2;
    int r1 = bb*SEQ + qb*128 + warp*16 + lr;
    int r2 = r1 + 8;
    #pragma unroll
    for (int nf = 0; nf < 8; nf++) {
        int col = (h<<6) + nf*8 + 2*lc;
        *(uint2*)(g_multi + (size_t)r1*KDIM + col) =
            make_uint2(f2tf(o[nf][0]*inv1), f2tf(o[nf][1]*inv1));
        *(uint2*)(g_multi + (size_t)r2*KDIM + col) =
            make_uint2(f2tf(o[nf][2]*inv2), f2tf(o[nf][3]*inv2));
    }
}

// ---------------------------------------------------------------------------
extern "C" void kernel_launch(void* const* d_in, const int* in_sizes, int n_in,
                              void* d_out, int out_size)
{
    const float* queries = (const float*)d_in[0];
    const float* context = (const float*)d_in[1];
    const float* Wq = (const float*)d_in[2];
    const float* bq = (const float*)d_in[3];
    const float* Wk = (const float*)d_in[4];
    const float* bk = (const float*)d_in[5];
    const float* Wv = (const float*)d_in[6];
    const float* bv = (const float*)d_in[7];
    const float* Wo = (const float*)d_in[8];
    const float* bo = (const float*)d_in[9];

    float* out = (float*)d_out;
    float* res = out + (size_t)MTOT * KDIM;

    static int attr_set = 0;
    if (!attr_set) {
        cudaFuncSetAttribute(gemmG<0>, cudaFuncAttributeMaxDynamicSharedMemorySize, 73728);
        cudaFuncSetAttribute(gemmG<1>, cudaFuncAttributeMaxDynamicSharedMemorySize, 73728);
        cudaFuncSetAttribute(attn_tc,  cudaFuncAttributeMaxDynamicSharedMemorySize, 69632);
        attr_set = 1;
    }

    // 1) round inputs; transpose+round weights
    cvt_in<<<8192, 256>>>(queries, context);
    wt_pre<<<4096, 256>>>(Wq, Wk, Wv, Wo);

    // 2) fused Q/K/V projections (Q -> res fp32, K/V -> scratch tf32)
    gemmG<0><<<dim3(24,32), 256, 73728>>>(out, bq, bk, bv, bo);
    // 3) attention -> g_multi
    attn_tc<<<dim3(8,64), 256, 69632>>>(res);
    // 4) output projection -> out
    gemmG<1><<<dim3(8,32), 256, 73728>>>(out, bq, bk, bv, bo);
}

// round 13
// speedup vs baseline: 1.0627x; 1.0627x over previous
#include <cuda_runtime.h>
#include <cstdint>

#define BATCH 4
#define SEQ   1024
#define HNUM  16
#define HDIM  64
#define MTOT  4096
#define KDIM  1024

// Scratch (tf32-bit patterns stored as unsigned)
__device__ unsigned g_qt[MTOT*KDIM];
__device__ unsigned g_ct[MTOT*KDIM];
__device__ unsigned g_wqT[KDIM*KDIM];   // [n][k] K-major transposed weights
__device__ unsigned g_wkT[KDIM*KDIM];
__device__ unsigned g_wvT[KDIM*KDIM];
__device__ unsigned g_woT[KDIM*KDIM];
__device__ unsigned g_k[BATCH*HNUM*SEQ*HDIM];   // [B,H,Lkv,64] tf32 bits
__device__ unsigned g_v[BATCH*HNUM*SEQ*HDIM];
__device__ unsigned g_multi[MTOT*KDIM];         // concat head outputs, tf32 bits

__device__ __forceinline__ unsigned f2tf(float x){
    unsigned r; asm("cvt.rna.tf32.f32 %0, %1;" : "=r"(r) : "f"(x)); return r;
}
__device__ __forceinline__ float ex2(float x){
    float r; asm("ex2.approx.ftz.f32 %0, %1;" : "=f"(r) : "f"(x)); return r;
}
__device__ __forceinline__ void mma8(float* c, const unsigned* a, const unsigned* b){
    asm volatile("mma.sync.aligned.m16n8k8.row.col.f32.tf32.tf32.f32 "
        "{%0,%1,%2,%3}, {%4,%5,%6,%7}, {%8,%9}, {%0,%1,%2,%3};"
        : "+f"(c[0]),"+f"(c[1]),"+f"(c[2]),"+f"(c[3])
        : "r"(a[0]),"r"(a[1]),"r"(a[2]),"r"(a[3]),"r"(b[0]),"r"(b[1]));
}
__device__ __forceinline__ void cpa16(unsigned dst, const void* src){
    asm volatile("cp.async.cg.shared.global [%0], [%1], 16;" :: "r"(dst), "l"(src));
}
__device__ __forceinline__ void ldsm4(unsigned* r, unsigned addr){
    asm volatile("ldmatrix.sync.aligned.m8n8.x4.shared.b16 {%0,%1,%2,%3}, [%4];"
        : "=r"(r[0]),"=r"(r[1]),"=r"(r[2]),"=r"(r[3]) : "r"(addr));
}
__device__ __forceinline__ void ldsm2(unsigned* r, unsigned addr){
    asm volatile("ldmatrix.sync.aligned.m8n8.x2.shared.b16 {%0,%1}, [%2];"
        : "=r"(r[0]),"=r"(r[1]) : "r"(addr));
}
#define CP_COMMIT asm volatile("cp.async.commit_group;")
#define CP_WAIT1  asm volatile("cp.async.wait_group 1;")
#define CP_WAIT0  asm volatile("cp.async.wait_group 0;")

// ---------------------------------------------------------------------------
// Pre-pass 1: round inputs to tf32 bit patterns
// ---------------------------------------------------------------------------
__global__ __launch_bounds__(256) void cvt_in(const float* __restrict__ q,
                                              const float* __restrict__ c)
{
    int i = blockIdx.x * 256 + threadIdx.x;   // float4 index, 2M total
    const float* s; unsigned* d; int off;
    if (i < 1048576) { s = q; d = g_qt; off = i; }
    else             { s = c; d = g_ct; off = i - 1048576; }
    float4 v = ((const float4*)s)[off];
    ((uint4*)d)[off] = make_uint4(f2tf(v.x), f2tf(v.y), f2tf(v.z), f2tf(v.w));
}

// ---------------------------------------------------------------------------
// Pre-pass 2: transpose + round weights -> dense K-major [n][k]. (Proven.)
// ---------------------------------------------------------------------------
__global__ __launch_bounds__(256) void wt_pre(const float* __restrict__ wq,
    const float* __restrict__ wk, const float* __restrict__ wv,
    const float* __restrict__ wo)
{
    __shared__ float t[32][33];
    int id = blockIdx.x;
    int tx = threadIdx.x & 31, ty = threadIdx.x >> 5;
    int mi = id >> 10, tl = id & 1023;

    if (mi < 3) {
        const float* src = (mi==0 ? wq : mi==1 ? wk : wv);
        unsigned* dst = (mi==0 ? g_wqT : mi==1 ? g_wkT : g_wvT);
        int h = tl >> 6, tt = tl & 63;
        int tc = tt & 1, tr = tt >> 1;
        src += (size_t)h * 65536;       // [1024][64]
        dst += (size_t)h * 65536;       // [64][1024]
        #pragma unroll
        for (int j = 0; j < 4; j++)
            t[ty + j*8][tx] = src[(size_t)(tr*32 + ty + j*8)*64 + tc*32 + tx];
        __syncthreads();
        #pragma unroll
        for (int j = 0; j < 4; j++)
            dst[(size_t)(tc*32 + ty + j*8)*1024 + tr*32 + tx] = f2tf(t[tx][ty + j*8]);
    } else {
        int tc = tl & 31, tr = tl >> 5;
        #pragma unroll
        for (int j = 0; j < 4; j++)
            t[ty + j*8][tx] = wo[(size_t)(tr*32 + ty + j*8)*1024 + tc*32 + tx];
        __syncthreads();
        #pragma unroll
        for (int j = 0; j < 4; j++)
            g_woT[(size_t)(tc*32 + ty + j*8)*1024 + tr*32 + tx] = f2tf(t[tx][ty + j*8]);
    }
}

// ---------------------------------------------------------------------------
// Legacy-HMMA tf32 GEMM (R10 winner shape) + ldmatrix fragment loads.
// CTA 64x128, 128 threads (4 warps of 32m x 64n), BK=32 double-buffered
// cp.async, occ 4 (16 warps/SM). Frag loads: A = ldmatrix.x4 (1 op/frag),
// B = ldmatrix.x2 (1 op/frag): 40 -> 26 issue slots per 16 mmas.
// PHASE 0: fused Q/K/V projections, grid.x=24 (sel = x>>3):
//          sel 0 -> fp32 Q to residual region; sel 1/2 -> tf32 K/V scratch.
// PHASE 1: out projection (A=g_multi, W=g_woT), fp32 + bo.
// ---------------------------------------------------------------------------
template<int PHASE>
__global__ __launch_bounds__(128,4) void gemmF(
    float* __restrict__ outbase,
    const float* __restrict__ bq, const float* __restrict__ bk,
    const float* __restrict__ bv, const float* __restrict__ bo)
{
    extern __shared__ unsigned sh[];        // A[2][64][36], B[2][128][36]
    unsigned* As = sh;                       // buffer stride 64*36
    unsigned* Bs = sh + 2*64*36;             // buffer stride 128*36
    const unsigned sA = (unsigned)__cvta_generic_to_shared(As);
    const unsigned sB = (unsigned)__cvta_generic_to_shared(Bs);

    int sel, nb;
    const unsigned *Ap, *Wp;
    const float* bias;
    if (PHASE == 0) {
        sel = blockIdx.x >> 3; nb = blockIdx.x & 7;
        Ap = (sel == 0) ? g_qt : g_ct;
        Wp = (sel == 0) ? g_wqT : (sel == 1) ? g_wkT : g_wvT;
        bias = (sel == 0) ? bq : (sel == 1) ? bk : bv;
    } else {
        sel = 0; nb = blockIdx.x;
        Ap = g_multi; Wp = g_woT; bias = bo;
    }
    const int n0 = nb << 7;                  // 128-wide n tile
    const int m0 = blockIdx.y << 6;          // 64-wide m tile

    const int tid = threadIdx.x;
    const int lane = tid & 31, warp = tid >> 5;
    const int wm = warp & 1, wn = warp >> 1; // 2x2 warps of 32m x 64n
    const int lr = lane >> 2, lc = lane & 3;

    // ldmatrix per-thread row addresses (byte offsets within a buffer)
    const int t8 = lane & 7, g = lane >> 3;
    // A x4: group g -> (row + (g&1)*8, col + (g>>1)*4)
    unsigned aoff[2];
    #pragma unroll
    for (int mi = 0; mi < 2; mi++)
        aoff[mi] = (unsigned)(((wm*32 + mi*16 + (g&1)*8 + t8)*36 + (g>>1)*4)*4);
    // B x2: lanes 0-7 col+0, lanes 8-15 col+4 (lanes>=16 ignored)
    const unsigned boff = (unsigned)(((wn*64 + t8)*36 + (g&1)*4)*4);

    float acc[2][8][4] = {};

    // fill tasks: A 512 chunks (4/thread), B 1024 chunks (8/thread); chunk=16B
    #define FILL(K0, BUFO)                                                    \
    {                                                                         \
        _Pragma("unroll")                                                     \
        for (int j = 0; j < 4; j++) {                                         \
            int c = tid + j*128, row = c >> 3, off = (c & 7) << 2;            \
            cpa16(sA + (unsigned)(((BUFO)*64*36 + row*36 + off)*4),           \
                  Ap + (size_t)(m0 + row)*KDIM + (K0) + off);                 \
        }                                                                     \
        _Pragma("unroll")                                                     \
        for (int j = 0; j < 8; j++) {                                         \
            int c = tid + j*128, row = c >> 3, off = (c & 7) << 2;            \
            cpa16(sB + (unsigned)(((BUFO)*128*36 + row*36 + off)*4),          \
                  Wp + (size_t)(n0 + row)*KDIM + (K0) + off);                 \
        }                                                                     \
        CP_COMMIT;                                                            \
    }

    FILL(0, 0);

    for (int it = 0; it < 32; it++) {
        const int b = it & 1;
        __syncthreads();                       // other buffer consumed
        if (it < 31) {
            FILL((it+1) << 5, b ^ 1);
            CP_WAIT1;
        } else {
            CP_WAIT0;
        }
        __syncthreads();                       // tile it visible

        const unsigned abase = sA + (unsigned)(b*64*36*4);
        const unsigned bbase = sB + (unsigned)(b*128*36*4);
        #pragma unroll
        for (int kk = 0; kk < 4; kk++) {
            const unsigned kb = (unsigned)(kk*32);   // 8 words = 32B per k-step
            unsigned a[2][4], bf[8][2];
            #pragma unroll
            for (int mi = 0; mi < 2; mi++)
                ldsm4(a[mi], abase + aoff[mi] + kb);
            #pragma unroll
            for (int nf = 0; nf < 8; nf++)
                ldsm2(bf[nf], bbase + boff + (unsigned)(nf*8*36*4) + kb);
            #pragma unroll
            for (int mi = 0; mi < 2; mi++)
                #pragma unroll
                for (int nf = 0; nf < 8; nf++)
                    mma8(acc[mi][nf], a[mi], bf[nf]);
        }
    }
    #undef FILL

    // epilogue
    #pragma unroll
    for (int mi = 0; mi < 2; mi++) {
        int r1 = m0 + wm*32 + mi*16 + lr;
        int r2 = r1 + 8;
        #pragma unroll
        for (int nf = 0; nf < 8; nf++) {
            int gcol = n0 + wn*64 + nf*8 + 2*lc;
            float b0 = bias[gcol], b1 = bias[gcol+1];
            float v00 = acc[mi][nf][0] + b0, v01 = acc[mi][nf][1] + b1;
            float v10 = acc[mi][nf][2] + b0, v11 = acc[mi][nf][3] + b1;
            if (PHASE == 1 || sel == 0) {
                float* dst = (PHASE == 1) ? outbase
                                          : outbase + (size_t)MTOT*KDIM;
                *(float2*)(dst + (size_t)r1*KDIM + gcol) = make_float2(v00, v01);
                *(float2*)(dst + (size_t)r2*KDIM + gcol) = make_float2(v10, v11);
            } else {
                unsigned* dst = (sel == 1) ? g_k : g_v;
                int h = gcol >> 6, wc = gcol & 63;
                *(uint2*)(dst + ((size_t)((r1 >> 10)*HNUM + h) << 16)
                              + (size_t)(r1 & 1023)*64 + wc) =
                    make_uint2(f2tf(v00), f2tf(v01));
                *(uint2*)(dst + ((size_t)((r2 >> 10)*HNUM + h) << 16)
                              + (size_t)(r2 & 1023)*64 + wc) =
                    make_uint2(f2tf(v10), f2tf(v11));
            }
        }
    }
}

// ---------------------------------------------------------------------------
// Per-warp flash attention (legacy tf32 mma) — unchanged from R4 (passing).
// ---------------------------------------------------------------------------
__global__ __launch_bounds__(256,2) void attn_tc(const float* __restrict__ Qres)
{
    extern __shared__ unsigned sh[];
    const unsigned sb = (unsigned)__cvta_generic_to_shared(sh);
    unsigned* Kb = sh;
    unsigned* Vb = sh + 2*64*68;
    const unsigned sbV = sb + 2*64*68*4;

    const int qb = blockIdx.x;
    const int bh = blockIdx.y;
    const int bb = bh >> 4, h = bh & 15;
    const int tid = threadIdx.x;
    const int lane = tid & 31, warp = tid >> 5;
    const int lr = lane >> 2, lc = lane & 3;

    const float SC = 0.125f * 1.44269504f;
    const float* qp = Qres + (size_t)(bb*SEQ + qb*128 + warp*16)*KDIM + (h<<6);
    unsigned Qa[8][4];
    #pragma unroll
    for (int kk = 0; kk < 8; kk++) {
        Qa[kk][0] = f2tf(SC * qp[(size_t)lr*KDIM     + kk*8 + lc]);
        Qa[kk][1] = f2tf(SC * qp[(size_t)(lr+8)*KDIM + kk*8 + lc]);
        Qa[kk][2] = f2tf(SC * qp[(size_t)lr*KDIM     + kk*8 + lc + 4]);
        Qa[kk][3] = f2tf(SC * qp[(size_t)(lr+8)*KDIM + kk*8 + lc + 4]);
    }

    const unsigned* kp = g_k + (size_t)bh*SEQ*HDIM;
    const unsigned* vp = g_v + (size_t)bh*SEQ*HDIM;
    const int krow = tid >> 4, kc4 = (tid & 15) << 2;

    {
        #pragma unroll
        for (int i = 0; i < 4; i++) {
            int r = krow + i*16;
            cpa16(sb  + (unsigned)((r*68 + kc4)*4), kp + r*64 + kc4);
            cpa16(sbV + (unsigned)((r*68 + kc4)*4), vp + r*64 + kc4);
        }
        CP_COMMIT;
    }

    float o[8][4] = {};
    float rm1 = -1e30f, rm2 = -1e30f, rl1 = 0.f, rl2 = 0.f;

    for (int kt = 0; kt < 16; kt++) {
        __syncthreads();
        if (kt < 15) {
            int buf = (kt+1) & 1;
            const unsigned* ks = kp + (size_t)(kt+1)*4096;
            const unsigned* vs = vp + (size_t)(kt+1)*4096;
            #pragma unroll
            for (int i = 0; i < 4; i++) {
                int r = krow + i*16;
                cpa16(sb  + (unsigned)(((buf*64 + r)*68 + kc4)*4), ks + r*64 + kc4);
                cpa16(sbV + (unsigned)(((buf*64 + r)*68 + kc4)*4), vs + r*64 + kc4);
            }
            CP_COMMIT;
            CP_WAIT1;
        } else {
            CP_WAIT0;
        }
        __syncthreads();

        const unsigned* K = Kb + (kt&1)*64*68;
        const unsigned* V = Vb + (kt&1)*64*68;

        float scf[8][4] = {};
        #pragma unroll
        for (int kk = 0; kk < 8; kk++) {
            #pragma unroll
            for (int nf = 0; nf < 8; nf++) {
                unsigned b[2];
                b[0] = K[(nf*8+lr)*68 + kk*8 + lc];
                b[1] = K[(nf*8+lr)*68 + kk*8 + lc + 4];
                mma8(scf[nf], Qa[kk], b);
            }
        }

        float m1 = -1e30f, m2 = -1e30f;
        #pragma unroll
        for (int nf = 0; nf < 8; nf++) {
            m1 = fmaxf(m1, fmaxf(scf[nf][0], scf[nf][1]));
            m2 = fmaxf(m2, fmaxf(scf[nf][2], scf[nf][3]));
        }
        m1 = fmaxf(m1, __shfl_xor_sync(0xffffffffu, m1, 1));
        m1 = fmaxf(m1, __shfl_xor_sync(0xffffffffu, m1, 2));
        m2 = fmaxf(m2, __shfl_xor_sync(0xffffffffu, m2, 1));
        m2 = fmaxf(m2, __shfl_xor_sync(0xffffffffu, m2, 2));
        float nm1 = fmaxf(rm1, m1), nm2 = fmaxf(rm2, m2);
        float cf1 = ex2(rm1 - nm1), cf2 = ex2(rm2 - nm2);
        rm1 = nm1; rm2 = nm2;

        float ls1 = 0.f, ls2 = 0.f;
        unsigned pa[8][4];
        #pragma unroll
        for (int nf = 0; nf < 8; nf++) {
            float p0 = ex2(scf[nf][0] - nm1); ls1 += p0;
            float p1 = ex2(scf[nf][1] - nm1); ls1 += p1;
            float p2 = ex2(scf[nf][2] - nm2); ls2 += p2;
            float p3 = ex2(scf[nf][3] - nm2); ls2 += p3;
            pa[nf][0] = f2tf(p0); pa[nf][1] = f2tf(p1);
            pa[nf][2] = f2tf(p2); pa[nf][3] = f2tf(p3);
        }
        ls1 += __shfl_xor_sync(0xffffffffu, ls1, 1);
        ls1 += __shfl_xor_sync(0xffffffffu, ls1, 2);
        ls2 += __shfl_xor_sync(0xffffffffu, ls2, 1);
        ls2 += __shfl_xor_sync(0xffffffffu, ls2, 2);
        rl1 = rl1*cf1 + ls1;
        rl2 = rl2*cf2 + ls2;

        #pragma unroll
        for (int nf = 0; nf < 8; nf++) {
            o[nf][0] *= cf1; o[nf][1] *= cf1;
            o[nf][2] *= cf2; o[nf][3] *= cf2;
        }

        #pragma unroll
        for (int kc = 0; kc < 8; kc++) {
            unsigned a[4] = { pa[kc][0], pa[kc][2], pa[kc][1], pa[kc][3] };
            #pragma unroll
            for (int nf = 0; nf < 8; nf++) {
                unsigned b[2];
                b[0] = V[(kc*8 + 2*lc    )*68 + nf*8 + lr];
                b[1] = V[(kc*8 + 2*lc + 1)*68 + nf*8 + lr];
                mma8(o[nf], a, b);
            }
        }
    }

    float inv1 = 1.f / rl1, inv2 = 1.f / rl2;
    int r1 = bb*SEQ + qb*128 + warp*16 + lr;
    int r2 = r1 + 8;
    #pragma unroll
    for (int nf = 0; nf < 8; nf++) {
        int col = (h<<6) + nf*8 + 2*lc;
        *(uint2*)(g_multi + (size_t)r1*KDIM + col) =
            make_uint2(f2tf(o[nf][0]*inv1), f2tf(o[nf][1]*inv1));
        *(uint2*)(g_multi + (size_t)r2*KDIM + col) =
            make_uint2(f2tf(o[nf][2]*inv2), f2tf(o[nf][3]*inv2));
    }
}

// ---------------------------------------------------------------------------
extern "C" void kernel_launch(void* const* d_in, const int* in_sizes, int n_in,
                              void* d_out, int out_size)
{
    const float* queries = (const float*)d_in[0];
    const float* context = (const float*)d_in[1];
    const float* Wq = (const float*)d_in[2];
    const float* bq = (const float*)d_in[3];
    const float* Wk = (const float*)d_in[4];
    const float* bk = (const float*)d_in[5];
    const float* Wv = (const float*)d_in[6];
    const float* bv = (const float*)d_in[7];
    const float* Wo = (const float*)d_in[8];
    const float* bo = (const float*)d_in[9];

    float* out = (float*)d_out;
    float* res = out + (size_t)MTOT * KDIM;

    static int attr_set = 0;
    if (!attr_set) {
        cudaFuncSetAttribute(gemmF<0>, cudaFuncAttributeMaxDynamicSharedMemorySize, 55296);
        cudaFuncSetAttribute(gemmF<1>, cudaFuncAttributeMaxDynamicSharedMemorySize, 55296);
        cudaFuncSetAttribute(attn_tc,  cudaFuncAttributeMaxDynamicSharedMemorySize, 69632);
        attr_set = 1;
    }

    // 1) round inputs; transpose+round weights
    cvt_in<<<8192, 256>>>(queries, context);
    wt_pre<<<4096, 256>>>(Wq, Wk, Wv, Wo);

    // 2) fused Q/K/V projections (Q -> res fp32, K/V -> scratch tf32)
    gemmF<0><<<dim3(24,64), 128, 55296>>>(out, bq, bk, bv, bo);
    // 3) attention -> g_multi
    attn_tc<<<dim3(8,64), 256, 69632>>>(res);
    // 4) output projection -> out
    gemmF<1><<<dim3(8,64), 128, 55296>>>(out, bq, bk, bv, bo);
}